// round 6
// baseline (speedup 1.0000x reference)
#include <cuda_runtime.h>
#include <math.h>

#define R 32
#define V 50257
#define VR (V * R)            // 1,608,224 floats per i-slab
#define BATCH 1024
#define NSTEP 8
#define EPS 1e-10f

#define THREADS 256
#define GATHER_BLOCKS 128     // 128 blocks * 8 warps = 1024 warps = 1 / batch row
#define RED_BX 24             // reduction blocks per i
#define RED_BLOCKS (RED_BX * R)               // 768
#define NBLOCKS (GATHER_BLOCKS + RED_BLOCKS)  // 896  (~one wave at 7 blocks/SM)
#define DEPTH 8               // cp.async pipeline stages (32KB smem ring)

// Scratch (no allocation allowed anywhere)
__device__ float g_Mpart[RED_BLOCKS * R];   // per-block partial sums of M
__device__ float g_pt[BATCH];               // prob_tilde per row
__device__ unsigned int g_count = 0;        // completion counter

__device__ __forceinline__ void cp_async16(unsigned smem_addr, const void* gptr) {
    asm volatile("cp.async.cg.shared.global [%0], [%1], 16;\n"
                 :: "r"(smem_addr), "l"(gptr) : "memory");
}
__device__ __forceinline__ void cp_commit() {
    asm volatile("cp.async.commit_group;\n" ::: "memory");
}
template <int N>
__device__ __forceinline__ void cp_wait() {
    asm volatile("cp.async.wait_group %0;\n" :: "n"(N) : "memory");
}

__global__ __launch_bounds__(THREADS)
void tjd_fused_kernel(const float* __restrict__ alpha,
                      const float* __restrict__ beta,
                      const float* __restrict__ core,
                      const int*   __restrict__ ids,
                      float* __restrict__ out, int out_size)
{
    const int bid = blockIdx.x;
    const int tid = threadIdx.x;

    // 32KB cp.async ring, unioned with finalize scratch (used strictly after
    // the ring is fully drained by the last block).
    __shared__ __align__(16) union SmemU {
        float4 buf[DEPTH][THREADS];                       // 32 KB
        struct { float sM[R * R]; float sloss[THREADS]; } fin;
    } u;
    __shared__ float sred[R];
    __shared__ float s_z;
    __shared__ int   s_last;

    if (bid < GATHER_BLOCKS) {
        // ---------------- gather/chain: one warp per batch row ----------------
        const int row  = bid * (THREADS / 32) + (tid >> 5);
        const int lane = tid & 31;
        const int* myids = ids + row * NSTEP;

        float v = fmaxf(alpha[lane], 0.0f) + EPS;   // lane holds v[lane]

        #pragma unroll 1
        for (int t = 0; t < NSTEP; t++) {
            const float* base = core + (size_t)myids[t] * R + lane;
            float g[R];
            #pragma unroll
            for (int i = 0; i < R; i++)
                g[i] = __ldg(base + (size_t)i * VR);
            float nv = 0.0f;
            #pragma unroll
            for (int i = 0; i < R; i++)
                nv = fmaf(__shfl_sync(0xffffffffu, v, i),
                          fmaxf(g[i], 0.0f) + EPS, nv);
            v = nv;
        }

        float pt = v * (fmaxf(beta[lane], 0.0f) + EPS);
        #pragma unroll
        for (int o = 16; o; o >>= 1)
            pt += __shfl_xor_sync(0xffffffffu, pt, o);
        if (lane == 0) g_pt[row] = pt;
    } else {
        // ------------- reduction: M[i][j] = sum_v relu(core[i,v,j]) -----------
        // cp.async pipeline: data never touches the register file in flight,
        // so MLP = DEPTH per thread regardless of ptxas register budget.
        const int rb = bid - GATHER_BLOCKS;
        const int i  = rb / RED_BX;
        const int bx = rb % RED_BX;

        const float4* p = (const float4*)(core + (size_t)i * VR);
        const int n4     = VR / 4;               // 402,056
        const int stride = RED_BX * THREADS;     // 6,144 (mult of 8 -> fixed j)

        // stages where ALL threads of this block are in bounds
        int nfull = (n4 - bx * THREADS - THREADS) / stride + 1;
        if (nfull < 0) nfull = 0;

        const unsigned slot0 =
            (unsigned)__cvta_generic_to_shared(&u.buf[0][tid]);
        const float4* gbase = p + bx * THREADS + tid;

        // prologue: fill the ring
        int issued = (nfull < DEPTH) ? nfull : DEPTH;
        #pragma unroll
        for (int s = 0; s < DEPTH; s++) {
            if (s < issued) {
                cp_async16(slot0 + (unsigned)s * (THREADS * 16),
                           gbase + (size_t)s * stride);
                cp_commit();
            }
        }

        float x0=0.f, y0=0.f, z0=0.f, w0=0.f;
        float x1=0.f, y1=0.f, z1=0.f, w1=0.f;

        // steady state: pending == DEPTH at loop top; wait(DEPTH-1) retires the
        // oldest stage; each thread touches only its own slot -> no barriers.
        int c = 0;
        while (issued < nfull) {
            cp_wait<DEPTH - 1>();
            float4 g = u.buf[c & (DEPTH - 1)][tid];
            if (c & 1) { x1 += fmaxf(g.x,0.f); y1 += fmaxf(g.y,0.f);
                         z1 += fmaxf(g.z,0.f); w1 += fmaxf(g.w,0.f); }
            else       { x0 += fmaxf(g.x,0.f); y0 += fmaxf(g.y,0.f);
                         z0 += fmaxf(g.z,0.f); w0 += fmaxf(g.w,0.f); }
            cp_async16(slot0 + (unsigned)(issued & (DEPTH - 1)) * (THREADS * 16),
                       gbase + (size_t)issued * stride);
            cp_commit();
            issued++; c++;
        }
        // drain
        cp_wait<0>();
        for (; c < nfull; c++) {
            float4 g = u.buf[c & (DEPTH - 1)][tid];
            x0 += fmaxf(g.x,0.f); y0 += fmaxf(g.y,0.f);
            z0 += fmaxf(g.z,0.f); w0 += fmaxf(g.w,0.f);
        }
        // ragged tail (at most one element per thread)
        {
            int idx = bx * THREADS + tid + nfull * stride;
            if (idx < n4) {
                float4 g = __ldg(p + idx);
                x1 += fmaxf(g.x,0.f); y1 += fmaxf(g.y,0.f);
                z1 += fmaxf(g.z,0.f); w1 += fmaxf(g.w,0.f);
            }
        }
        const float ax = x0 + x1, ay = y0 + y1, az = z0 + z1, aw = w0 + w1;

        if (tid < R) sred[tid] = 0.0f;
        __syncthreads();
        const int jb = (tid & 7) * 4;
        atomicAdd(&sred[jb + 0], ax);
        atomicAdd(&sred[jb + 1], ay);
        atomicAdd(&sred[jb + 2], az);
        atomicAdd(&sred[jb + 3], aw);
        __syncthreads();
        if (tid < R)
            g_Mpart[rb * R + tid] = sred[tid];
    }

    // ------------------- last-block-done finalize -------------------
    __syncthreads();
    if (tid == 0) {
        __threadfence();                   // make partials/g_pt visible
        s_last = (atomicAdd(&g_count, 1u) == (unsigned)(NBLOCKS - 1));
    }
    __syncthreads();
    if (!s_last) return;

    // sum the RED_BX partials per M entry; fold per-element eps back in
    for (int e = tid; e < R * R; e += THREADS) {
        const int i = e >> 5, j = e & 31;
        float s = 0.0f;
        #pragma unroll 8
        for (int b = 0; b < RED_BX; b++)
            s += g_Mpart[(i * RED_BX + b) * R + j];
        u.fin.sM[e] = s + (float)V * EPS;
    }
    __syncthreads();

    // z = a (M)^8 b  (warp 0; overflows to +inf ~step 7 exactly like fp32 ref)
    if (tid < R) {
        float uu = fmaxf(alpha[tid], 0.0f) + EPS;
        #pragma unroll 1
        for (int s = 0; s < NSTEP; s++) {
            float nu = 0.0f;
            #pragma unroll
            for (int i = 0; i < R; i++)
                nu = fmaf(__shfl_sync(0xffffffffu, uu, i),
                          u.fin.sM[i * R + tid], nu);
            uu = nu;
        }
        float z = uu * (fmaxf(beta[tid], 0.0f) + EPS);
        #pragma unroll
        for (int o = 16; o; o >>= 1)
            z += __shfl_xor_sync(0xffffffffu, z, o);
        if (tid == 0) s_z = z;
    }
    __syncthreads();

    const float z = s_z;
    float lacc = 0.0f;
    for (int row = tid; row < BATCH; row += THREADS) {
        const float prob = g_pt[row] / z;           // finite/inf -> 0 like ref
        if (out_size >= BATCH + 1)  out[1 + row] = prob;   // [loss, prob...]
        else if (out_size == BATCH) out[row]     = prob;   // prob only
        lacc -= logf(prob + EPS);
    }
    u.fin.sloss[tid] = lacc;
    __syncthreads();
    #pragma unroll
    for (int s = THREADS / 2; s > 0; s >>= 1) {
        if (tid < s) u.fin.sloss[tid] += u.fin.sloss[tid + s];
        __syncthreads();
    }
    if (tid == 0) {
        if (out_size != BATCH) out[0] = u.fin.sloss[0] / (float)BATCH;
        g_count = 0;                        // reset for next graph replay
    }
}

// ---------------------------------------------------------------------------
extern "C" void kernel_launch(void* const* d_in, const int* in_sizes, int n_in,
                              void* d_out, int out_size) {
    const float* alpha = (const float*)d_in[0];   // (32,)
    const float* beta  = (const float*)d_in[1];   // (32,)
    const float* core  = (const float*)d_in[2];   // (32, 50257, 32)
    const int*   ids   = (const int*)  d_in[3];   // (1024, 8)

    tjd_fused_kernel<<<NBLOCKS, THREADS>>>(alpha, beta, core, ids,
                                           (float*)d_out, out_size);
}